// round 1
// baseline (speedup 1.0000x reference)
#include <cuda_runtime.h>
#include <math.h>

// KDLayerNorm: per-row kernel-density CDF -> Gaussian PPF normalization.
// x: [4, 1024, 256] fp32, weight/bias: [256].
// For each row r (4096 rows of D=256):
//   bw  = 0.9 * std(row, ddof=1) * 256^(-0.2)
//   cdf_i = (1/D) sum_j 0.5*(1+erf((x_i-x_j)/(bw*sqrt2)))
//   out_i = erfinv(2*cdf_i - 1)*sqrt2 * w_i + b_i
// Note 2*cdf_i-1 = (1/D) * sum_j erf((x_i-x_j)/(bw*sqrt2)).

#define D 256

__global__ __launch_bounds__(D, 8)
void kdln_kernel(const float* __restrict__ x,
                 const float* __restrict__ weight,
                 const float* __restrict__ bias,
                 float* __restrict__ out)
{
    __shared__ float sxs[D];       // pre-scaled row values
    __shared__ float wsum[8], wsq[8];

    const int row = blockIdx.x;
    const int tid = threadIdx.x;

    const float v = x[row * D + tid];

    // --- row mean / var (ddof=1) via warp + block reduction ---
    float s = v, s2 = v * v;
    #pragma unroll
    for (int o = 16; o > 0; o >>= 1) {
        s  += __shfl_xor_sync(0xFFFFFFFFu, s,  o);
        s2 += __shfl_xor_sync(0xFFFFFFFFu, s2, o);
    }
    if ((tid & 31) == 0) { wsum[tid >> 5] = s; wsq[tid >> 5] = s2; }
    __syncthreads();

    float S = 0.f, S2 = 0.f;
    #pragma unroll
    for (int i = 0; i < 8; i++) { S += wsum[i]; S2 += wsq[i]; }

    const float mean = S * (1.0f / D);
    const float var  = (S2 - (float)D * mean * mean) * (1.0f / (D - 1));
    // 0.9 * 256^(-0.2) = 0.9 * 0.32987697769322634 = 0.2968892799239037
    const float bw   = 0.2968892799239037f * sqrtf(var);
    const float inv  = 1.0f / (bw * 1.4142135623730951f);  // 1/(bw*sqrt2)

    const float myv = v * inv;
    sxs[tid] = myv;
    __syncthreads();

    // --- pairwise erf accumulation ---
    float acc = 0.0f;
    #pragma unroll 8
    for (int j = 0; j < D; j++) {
        acc += erff(myv - sxs[j]);
    }

    // 2*cdf - 1 = acc / D
    const float normed = erfinvf(acc * (1.0f / D)) * 1.4142135623730951f;
    out[row * D + tid] = normed * weight[tid] + bias[tid];
}

extern "C" void kernel_launch(void* const* d_in, const int* in_sizes, int n_in,
                              void* d_out, int out_size)
{
    const float* x = (const float*)d_in[0];
    const float* w = (const float*)d_in[1];
    const float* b = (const float*)d_in[2];
    float* out = (float*)d_out;

    const int n_rows = in_sizes[0] / D;   // 4096
    kdln_kernel<<<n_rows, D>>>(x, w, b, out);
}

// round 2
// speedup vs baseline: 2.8047x; 2.8047x over previous
#include <cuda_runtime.h>
#include <math.h>

// KDLayerNorm: per-row kernel-density CDF -> Gaussian PPF normalization.
// 2*cdf_i - 1 = (1/D) * sum_j erf((x_i-x_j)/(bw*sqrt2))
// erf approximated as tanh(x*(c0 + c1 s + c2 s^2 + c3 s^3)), s = x^2, |x| clamped to 3.5.
// Polynomial evaluated 2-wide with Blackwell f32x2 packed FMA; saturation via MUFU tanh.

#define D 256

typedef unsigned long long u64;

__device__ __forceinline__ float tanh_fast(float x) {
    float y; asm("tanh.approx.f32 %0, %1;" : "=f"(y) : "f"(x)); return y;
}
__device__ __forceinline__ u64 pack2(float lo, float hi) {
    u64 r; asm("mov.b64 %0, {%1, %2};" : "=l"(r) : "f"(lo), "f"(hi)); return r;
}
__device__ __forceinline__ void unpack2(u64 v, float& lo, float& hi) {
    asm("mov.b64 {%0, %1}, %2;" : "=f"(lo), "=f"(hi) : "l"(v));
}
__device__ __forceinline__ u64 add2(u64 a, u64 b) {
    u64 r; asm("add.rn.f32x2 %0, %1, %2;" : "=l"(r) : "l"(a), "l"(b)); return r;
}
__device__ __forceinline__ u64 mul2(u64 a, u64 b) {
    u64 r; asm("mul.rn.f32x2 %0, %1, %2;" : "=l"(r) : "l"(a), "l"(b)); return r;
}
__device__ __forceinline__ u64 fma2(u64 a, u64 b, u64 c) {
    u64 r; asm("fma.rn.f32x2 %0, %1, %2, %3;" : "=l"(r) : "l"(a), "l"(b), "l"(c)); return r;
}

// atanh(erf(x))/x cubic-in-x^2 fit (interp at s=0,1,4,9; clamp at |x|=3.5)
#define EC0 1.1283792f
#define EC1 0.10381686f
#define EC2 (-0.00175607f)
#define EC3 (-2.4992e-5f)

__global__ __launch_bounds__(D, 8)
void kdln_kernel(const float* __restrict__ x,
                 const float* __restrict__ weight,
                 const float* __restrict__ bias,
                 float* __restrict__ out)
{
    __shared__ float sneg[D];      // negated pre-scaled row values
    __shared__ float wsum[8], wsq[8];

    const int row = blockIdx.x;
    const int tid = threadIdx.x;

    const float v = x[row * D + tid];

    // --- row mean / var (ddof=1) ---
    float s = v, s2 = v * v;
    #pragma unroll
    for (int o = 16; o > 0; o >>= 1) {
        s  += __shfl_xor_sync(0xFFFFFFFFu, s,  o);
        s2 += __shfl_xor_sync(0xFFFFFFFFu, s2, o);
    }
    if ((tid & 31) == 0) { wsum[tid >> 5] = s; wsq[tid >> 5] = s2; }
    __syncthreads();

    float S = 0.f, S2 = 0.f;
    #pragma unroll
    for (int i = 0; i < 8; i++) { S += wsum[i]; S2 += wsq[i]; }

    const float mean = S * (1.0f / D);
    const float var  = (S2 - (float)D * mean * mean) * (1.0f / (D - 1));
    // 0.9 * 256^(-0.2) = 0.2968892799239037
    const float bw   = 0.2968892799239037f * sqrtf(var);
    const float inv  = 1.0f / (bw * 1.4142135623730951f);  // 1/(bw*sqrt2)

    const float myv = v * inv;
    sneg[tid] = -myv;
    __syncthreads();

    const u64 my2 = pack2(myv, myv);
    const u64 C0  = pack2(EC0, EC0);
    const u64 C1  = pack2(EC1, EC1);
    const u64 C2  = pack2(EC2, EC2);
    const u64 C3  = pack2(EC3, EC3);

    const u64* __restrict__ sp = (const u64*)sneg;   // 128 packed pairs

    float acc0 = 0.f, acc1 = 0.f, acc2 = 0.f, acc3 = 0.f;

    #pragma unroll 8
    for (int j = 0; j < D / 4; j++) {
        // --- pair A ---
        {
            u64 t = add2(my2, sp[2 * j]);
            float tl, th; unpack2(t, tl, th);
            tl = fminf(fmaxf(tl, -3.5f), 3.5f);
            th = fminf(fmaxf(th, -3.5f), 3.5f);
            t = pack2(tl, th);
            u64 sq = mul2(t, t);
            u64 q  = fma2(sq, C3, C2);
            q = fma2(q, sq, C1);
            q = fma2(q, sq, C0);
            u64 p = mul2(q, t);
            float pl, ph; unpack2(p, pl, ph);
            acc0 += tanh_fast(pl);
            acc1 += tanh_fast(ph);
        }
        // --- pair B (independent chain) ---
        {
            u64 t = add2(my2, sp[2 * j + 1]);
            float tl, th; unpack2(t, tl, th);
            tl = fminf(fmaxf(tl, -3.5f), 3.5f);
            th = fminf(fmaxf(th, -3.5f), 3.5f);
            t = pack2(tl, th);
            u64 sq = mul2(t, t);
            u64 q  = fma2(sq, C3, C2);
            q = fma2(q, sq, C1);
            q = fma2(q, sq, C0);
            u64 p = mul2(q, t);
            float pl, ph; unpack2(p, pl, ph);
            acc2 += tanh_fast(pl);
            acc3 += tanh_fast(ph);
        }
    }

    const float acc = (acc0 + acc1) + (acc2 + acc3);

    // 2*cdf - 1 = acc / D
    const float normed = erfinvf(acc * (1.0f / D)) * 1.4142135623730951f;
    out[row * D + tid] = normed * weight[tid] + bias[tid];
}

extern "C" void kernel_launch(void* const* d_in, const int* in_sizes, int n_in,
                              void* d_out, int out_size)
{
    const float* x = (const float*)d_in[0];
    const float* w = (const float*)d_in[1];
    const float* b = (const float*)d_in[2];
    float* out = (float*)d_out;

    const int n_rows = in_sizes[0] / D;   // 4096
    kdln_kernel<<<n_rows, D>>>(x, w, b, out);
}

// round 3
// speedup vs baseline: 3.1213x; 1.1129x over previous
#include <cuda_runtime.h>
#include <math.h>

// KDLayerNorm: per-row kernel-density CDF -> Gaussian PPF normalization.
// 2*cdf_i - 1 = (1/D) * sum_j erf((x_i-x_j)/(bw*sqrt2))
// erf(t) ~= tanh(t * q(min(t^2, 12.25))), q cubic. Packed f32x2 math + MUFU tanh.

#define D 256

typedef unsigned long long u64;

__device__ __forceinline__ float tanh_fast(float x) {
    float y; asm("tanh.approx.f32 %0, %1;" : "=f"(y) : "f"(x)); return y;
}
__device__ __forceinline__ u64 pack2(float lo, float hi) {
    u64 r; asm("mov.b64 %0, {%1, %2};" : "=l"(r) : "f"(lo), "f"(hi)); return r;
}
__device__ __forceinline__ void unpack2(u64 v, float& lo, float& hi) {
    asm("mov.b64 {%0, %1}, %2;" : "=f"(lo), "=f"(hi) : "l"(v));
}
__device__ __forceinline__ u64 add2(u64 a, u64 b) {
    u64 r; asm("add.rn.f32x2 %0, %1, %2;" : "=l"(r) : "l"(a), "l"(b)); return r;
}
__device__ __forceinline__ u64 mul2(u64 a, u64 b) {
    u64 r; asm("mul.rn.f32x2 %0, %1, %2;" : "=l"(r) : "l"(a), "l"(b)); return r;
}
__device__ __forceinline__ u64 fma2(u64 a, u64 b, u64 c) {
    u64 r; asm("fma.rn.f32x2 %0, %1, %2, %3;" : "=l"(r) : "l"(a), "l"(b), "l"(c)); return r;
}

// atanh(erf(x))/x cubic-in-x^2 fit (interp at s=0,1,4,9; s clamped at 12.25)
#define EC0 1.1283792f
#define EC1 0.10381686f
#define EC2 (-0.00175607f)
#define EC3 (-2.4992e-5f)
#define SMAX 12.25f

__global__ __launch_bounds__(D, 8)
void kdln_kernel(const float* __restrict__ x,
                 const float* __restrict__ weight,
                 const float* __restrict__ bias,
                 float* __restrict__ out)
{
    __shared__ __align__(16) float sneg[D];   // negated pre-scaled row values
    __shared__ float wsum[8], wsq[8];

    const int row = blockIdx.x;
    const int tid = threadIdx.x;

    const float v = x[row * D + tid];

    // --- row mean / var (ddof=1) ---
    float s = v, s2 = v * v;
    #pragma unroll
    for (int o = 16; o > 0; o >>= 1) {
        s  += __shfl_xor_sync(0xFFFFFFFFu, s,  o);
        s2 += __shfl_xor_sync(0xFFFFFFFFu, s2, o);
    }
    if ((tid & 31) == 0) { wsum[tid >> 5] = s; wsq[tid >> 5] = s2; }
    __syncthreads();

    float S = 0.f, S2 = 0.f;
    #pragma unroll
    for (int i = 0; i < 8; i++) { S += wsum[i]; S2 += wsq[i]; }

    const float mean = S * (1.0f / D);
    const float var  = (S2 - (float)D * mean * mean) * (1.0f / (D - 1));
    // 0.9 * 256^(-0.2) = 0.2968892799239037
    const float bw   = 0.2968892799239037f * sqrtf(var);
    const float inv  = 1.0f / (bw * 1.4142135623730951f);  // 1/(bw*sqrt2)

    const float myv = v * inv;
    sneg[tid] = -myv;
    __syncthreads();

    const u64 my2 = pack2(myv, myv);
    const u64 C0  = pack2(EC0, EC0);
    const u64 C1  = pack2(EC1, EC1);
    const u64 C2  = pack2(EC2, EC2);
    const u64 C3  = pack2(EC3, EC3);

    const float4* __restrict__ sp4 = (const float4*)sneg;  // 64 quads

    u64 accA = 0ull, accB = 0ull;   // packed {0.0f, 0.0f}

    #pragma unroll 8
    for (int j = 0; j < D / 4; j++) {
        const float4 w4 = sp4[j];
        // --- pair A: elems {x, y} ---
        {
            u64 t  = add2(my2, pack2(w4.x, w4.y));
            u64 sq = mul2(t, t);
            float sl, sh; unpack2(sq, sl, sh);
            sl = fminf(sl, SMAX);
            sh = fminf(sh, SMAX);
            u64 sc = pack2(sl, sh);
            u64 q  = fma2(sc, C3, C2);
            q = fma2(q, sc, C1);
            q = fma2(q, sc, C0);
            u64 p = mul2(q, t);
            float pl, ph; unpack2(p, pl, ph);
            accA = add2(accA, pack2(tanh_fast(pl), tanh_fast(ph)));
        }
        // --- pair B: elems {z, w} ---
        {
            u64 t  = add2(my2, pack2(w4.z, w4.w));
            u64 sq = mul2(t, t);
            float sl, sh; unpack2(sq, sl, sh);
            sl = fminf(sl, SMAX);
            sh = fminf(sh, SMAX);
            u64 sc = pack2(sl, sh);
            u64 q  = fma2(sc, C3, C2);
            q = fma2(q, sc, C1);
            q = fma2(q, sc, C0);
            u64 p = mul2(q, t);
            float pl, ph; unpack2(p, pl, ph);
            accB = add2(accB, pack2(tanh_fast(pl), tanh_fast(ph)));
        }
    }

    u64 accP = add2(accA, accB);
    float a0, a1; unpack2(accP, a0, a1);
    const float acc = a0 + a1;

    // 2*cdf - 1 = acc / D
    const float normed = erfinvf(acc * (1.0f / D)) * 1.4142135623730951f;
    out[row * D + tid] = normed * weight[tid] + bias[tid];
}

extern "C" void kernel_launch(void* const* d_in, const int* in_sizes, int n_in,
                              void* d_out, int out_size)
{
    const float* x = (const float*)d_in[0];
    const float* w = (const float*)d_in[1];
    const float* b = (const float*)d_in[2];
    float* out = (float*)d_out;

    const int n_rows = in_sizes[0] / D;   // 4096
    kdln_kernel<<<n_rows, D>>>(x, w, b, out);
}

// round 4
// speedup vs baseline: 3.2811x; 1.0512x over previous
#include <cuda_runtime.h>
#include <math.h>

// KDLayerNorm: per-row kernel-density CDF -> Gaussian PPF normalization.
// 2*cdf_i - 1 = (1/D) * sum_j erf((x_i-x_j)/(bw*sqrt2))
// erf(t) ~= tanh(t * q(min(t^2, 12.25))), q QUADRATIC. Packed f32x2 + MUFU tanh.
// 4 independent packed accumulator chains for ILP.

#define D 256

typedef unsigned long long u64;

__device__ __forceinline__ float tanh_fast(float x) {
    float y; asm("tanh.approx.f32 %0, %1;" : "=f"(y) : "f"(x)); return y;
}
__device__ __forceinline__ u64 pack2(float lo, float hi) {
    u64 r; asm("mov.b64 %0, {%1, %2};" : "=l"(r) : "f"(lo), "f"(hi)); return r;
}
__device__ __forceinline__ void unpack2(u64 v, float& lo, float& hi) {
    asm("mov.b64 {%0, %1}, %2;" : "=f"(lo), "=f"(hi) : "l"(v));
}
__device__ __forceinline__ u64 add2(u64 a, u64 b) {
    u64 r; asm("add.rn.f32x2 %0, %1, %2;" : "=l"(r) : "l"(a), "l"(b)); return r;
}
__device__ __forceinline__ u64 mul2(u64 a, u64 b) {
    u64 r; asm("mul.rn.f32x2 %0, %1, %2;" : "=l"(r) : "l"(a), "l"(b)); return r;
}
__device__ __forceinline__ u64 fma2(u64 a, u64 b, u64 c) {
    u64 r; asm("fma.rn.f32x2 %0, %1, %2, %3;" : "=l"(r) : "l"(a), "l"(b), "l"(c)); return r;
}

// atanh(erf(x))/x quadratic-in-x^2 fit (interp at s=0, 2.25, 9; s clamped at 12.25)
#define QC0 1.1283792f
#define QC1 0.104728f
#define QC2 (-0.00208245f)
#define SMAX 12.25f

__device__ __forceinline__ void erf2_acc(u64& acc, u64 my2, float e0, float e1,
                                         u64 C0, u64 C1, u64 C2)
{
    u64 t  = add2(my2, pack2(e0, e1));
    u64 sq = mul2(t, t);
    float sl, sh; unpack2(sq, sl, sh);
    sl = fminf(sl, SMAX);
    sh = fminf(sh, SMAX);
    u64 sc = pack2(sl, sh);
    u64 q  = fma2(sc, C2, C1);
    q = fma2(q, sc, C0);
    u64 p = mul2(q, t);
    float pl, ph; unpack2(p, pl, ph);
    acc = add2(acc, pack2(tanh_fast(pl), tanh_fast(ph)));
}

__global__ __launch_bounds__(D, 8)
void kdln_kernel(const float* __restrict__ x,
                 const float* __restrict__ weight,
                 const float* __restrict__ bias,
                 float* __restrict__ out)
{
    __shared__ __align__(16) float sneg[D];   // negated pre-scaled row values
    __shared__ float wsum[8], wsq[8];

    const int row = blockIdx.x;
    const int tid = threadIdx.x;

    const float v = x[row * D + tid];

    // --- row mean / var (ddof=1) ---
    float s = v, s2 = v * v;
    #pragma unroll
    for (int o = 16; o > 0; o >>= 1) {
        s  += __shfl_xor_sync(0xFFFFFFFFu, s,  o);
        s2 += __shfl_xor_sync(0xFFFFFFFFu, s2, o);
    }
    if ((tid & 31) == 0) { wsum[tid >> 5] = s; wsq[tid >> 5] = s2; }
    __syncthreads();

    float S = 0.f, S2 = 0.f;
    #pragma unroll
    for (int i = 0; i < 8; i++) { S += wsum[i]; S2 += wsq[i]; }

    const float mean = S * (1.0f / D);
    const float var  = (S2 - (float)D * mean * mean) * (1.0f / (D - 1));
    // 0.9 * 256^(-0.2) = 0.2968892799239037
    const float bw   = 0.2968892799239037f * sqrtf(var);
    const float inv  = 1.0f / (bw * 1.4142135623730951f);  // 1/(bw*sqrt2)

    const float myv = v * inv;
    sneg[tid] = -myv;
    __syncthreads();

    const u64 my2 = pack2(myv, myv);
    const u64 C0  = pack2(QC0, QC0);
    const u64 C1  = pack2(QC1, QC1);
    const u64 C2  = pack2(QC2, QC2);

    const float4* __restrict__ sp4 = (const float4*)sneg;  // 64 quads

    u64 accA = 0ull, accB = 0ull, accC = 0ull, accD = 0ull;

    #pragma unroll 4
    for (int it = 0; it < D / 8; it++) {
        const float4 wa = sp4[2 * it];
        const float4 wb = sp4[2 * it + 1];
        erf2_acc(accA, my2, wa.x, wa.y, C0, C1, C2);
        erf2_acc(accB, my2, wa.z, wa.w, C0, C1, C2);
        erf2_acc(accC, my2, wb.x, wb.y, C0, C1, C2);
        erf2_acc(accD, my2, wb.z, wb.w, C0, C1, C2);
    }

    u64 accP = add2(add2(accA, accB), add2(accC, accD));
    float a0, a1; unpack2(accP, a0, a1);
    const float acc = a0 + a1;

    // 2*cdf - 1 = acc / D
    const float normed = erfinvf(acc * (1.0f / D)) * 1.4142135623730951f;
    out[row * D + tid] = normed * weight[tid] + bias[tid];
}

extern "C" void kernel_launch(void* const* d_in, const int* in_sizes, int n_in,
                              void* d_out, int out_size)
{
    const float* x = (const float*)d_in[0];
    const float* w = (const float*)d_in[1];
    const float* b = (const float*)d_in[2];
    float* out = (float*)d_out;

    const int n_rows = in_sizes[0] / D;   // 4096
    kdln_kernel<<<n_rows, D>>>(x, w, b, out);
}

// round 5
// speedup vs baseline: 3.5447x; 1.0803x over previous
#include <cuda_runtime.h>
#include <math.h>

// KDLayerNorm: per-row kernel-density CDF -> Gaussian PPF normalization.
// 2*cdf_i - 1 = (1/D) * sum_j erf((x_i-x_j)/(bw*sqrt2))
// erf(t) ~= tanh(t * q(min(t^2,12.25))), q quadratic; packed f32x2 + MUFU tanh.
// Antisymmetry: each erf serves two accumulators (thread i and thread (i+d)%256)
// via a shared-memory exchange, halving MUFU (tanh) work.

#define D 256
#define CW 16              // offsets per exchange chunk
#define NCH (128 / CW)     // 8 chunks cover d = 1..128

typedef unsigned long long u64;

__device__ __forceinline__ float tanh_fast(float x) {
    float y; asm("tanh.approx.f32 %0, %1;" : "=f"(y) : "f"(x)); return y;
}
__device__ __forceinline__ u64 pack2(float lo, float hi) {
    u64 r; asm("mov.b64 %0, {%1, %2};" : "=l"(r) : "f"(lo), "f"(hi)); return r;
}
__device__ __forceinline__ void unpack2(u64 v, float& lo, float& hi) {
    asm("mov.b64 {%0, %1}, %2;" : "=f"(lo), "=f"(hi) : "l"(v));
}
__device__ __forceinline__ u64 add2(u64 a, u64 b) {
    u64 r; asm("add.rn.f32x2 %0, %1, %2;" : "=l"(r) : "l"(a), "l"(b)); return r;
}
__device__ __forceinline__ u64 mul2(u64 a, u64 b) {
    u64 r; asm("mul.rn.f32x2 %0, %1, %2;" : "=l"(r) : "l"(a), "l"(b)); return r;
}
__device__ __forceinline__ u64 fma2(u64 a, u64 b, u64 c) {
    u64 r; asm("fma.rn.f32x2 %0, %1, %2, %3;" : "=l"(r) : "l"(a), "l"(b), "l"(c)); return r;
}

// atanh(erf(x))/x quadratic-in-x^2 fit (interp at s=0, 2.25, 9; s clamped at 12.25)
#define QC0 1.1283792f
#define QC1 0.104728f
#define QC2 (-0.00208245f)
#define SMAX 12.25f

__global__ __launch_bounds__(D, 8)
void kdln_kernel(const float* __restrict__ x,
                 const float* __restrict__ weight,
                 const float* __restrict__ bias,
                 float* __restrict__ out)
{
    __shared__ __align__(16) float sdup[2 * D];  // negated scaled row, duplicated (wrap-free)
    __shared__ float sf[CW][D];                  // per-chunk erf exchange buffer
    __shared__ float wsum[8], wsq[8];

    const int row = blockIdx.x;
    const int tid = threadIdx.x;

    const float v = x[row * D + tid];

    // --- row mean / var (ddof=1) ---
    float s = v, s2 = v * v;
    #pragma unroll
    for (int o = 16; o > 0; o >>= 1) {
        s  += __shfl_xor_sync(0xFFFFFFFFu, s,  o);
        s2 += __shfl_xor_sync(0xFFFFFFFFu, s2, o);
    }
    if ((tid & 31) == 0) { wsum[tid >> 5] = s; wsq[tid >> 5] = s2; }
    __syncthreads();

    float S = 0.f, S2 = 0.f;
    #pragma unroll
    for (int i = 0; i < 8; i++) { S += wsum[i]; S2 += wsq[i]; }

    const float mean = S * (1.0f / D);
    const float var  = (S2 - (float)D * mean * mean) * (1.0f / (D - 1));
    // 0.9 * 256^(-0.2) = 0.2968892799239037
    const float bw   = 0.2968892799239037f * sqrtf(var);
    const float inv  = 1.0f / (bw * 1.4142135623730951f);  // 1/(bw*sqrt2)

    const float myv = v * inv;
    sdup[tid]     = -myv;
    sdup[tid + D] = -myv;
    __syncthreads();

    const u64 my2 = pack2(myv, myv);
    const u64 C0  = pack2(QC0, QC0);
    const u64 C1  = pack2(QC1, QC1);
    const u64 C2  = pack2(QC2, QC2);

    u64 accP0 = 0ull, accP1 = 0ull;   // + side (direct terms, d = 1..128)
    u64 accM0 = 0ull, accM1 = 0ull;   // - side (exchanged terms, d = 1..127)

    for (int c = 0; c < NCH; c++) {
        const int dbase = c * CW + 1;

        // --- compute phase: f_d(i) = erf((x_i - x_{i+d}) * inv), d = dbase..dbase+15 ---
        #pragma unroll
        for (int u = 0; u < CW / 2; u++) {
            const int d = dbase + 2 * u;
            u64 t  = add2(my2, pack2(sdup[tid + d], sdup[tid + d + 1]));
            u64 sq = mul2(t, t);
            float sl, sh; unpack2(sq, sl, sh);
            sl = fminf(sl, SMAX);
            sh = fminf(sh, SMAX);
            u64 sc = pack2(sl, sh);
            u64 q  = fma2(sc, C2, C1);
            q = fma2(q, sc, C0);
            u64 p = mul2(q, t);
            float pl, ph; unpack2(p, pl, ph);
            const float fl = tanh_fast(pl);
            const float fh = tanh_fast(ph);
            sf[2 * u][tid]     = fl;
            sf[2 * u + 1][tid] = fh;
            const u64 fp = pack2(fl, fh);
            if (u & 1) accP1 = add2(accP1, fp);
            else       accP0 = add2(accP0, fp);
        }
        __syncthreads();

        // --- exchange phase: thread i picks up -e_{i, i-d} = f_d((i-d) mod 256) ---
        #pragma unroll
        for (int u = 0; u < CW / 2; u++) {
            const int d = dbase + 2 * u;
            float g0 = sf[2 * u][(tid - d) & (D - 1)];
            float g1 = sf[2 * u + 1][(tid - d - 1) & (D - 1)];
            if (d + 1 == 128) g1 = 0.0f;   // d=128 pair is self-dual: add-only
            const u64 gp = pack2(g0, g1);
            if (u & 1) accM1 = add2(accM1, gp);
            else       accM0 = add2(accM0, gp);
        }
        __syncthreads();   // sf reused next chunk
    }

    float p0, p1, m0, m1;
    {
        u64 ap = add2(accP0, accP1);
        u64 am = add2(accM0, accM1);
        unpack2(ap, p0, p1);
        unpack2(am, m0, m1);
    }
    const float acc = (p0 + p1) - (m0 + m1);

    // 2*cdf - 1 = acc / D
    const float normed = erfinvf(acc * (1.0f / D)) * 1.4142135623730951f;
    out[row * D + tid] = normed * weight[tid] + bias[tid];
}

extern "C" void kernel_launch(void* const* d_in, const int* in_sizes, int n_in,
                              void* d_out, int out_size)
{
    const float* x = (const float*)d_in[0];
    const float* w = (const float*)d_in[1];
    const float* b = (const float*)d_in[2];
    float* out = (float*)d_out;

    const int n_rows = in_sizes[0] / D;   // 4096
    kdln_kernel<<<n_rows, D>>>(x, w, b, out);
}